// round 7
// baseline (speedup 1.0000x reference)
#include <cuda_runtime.h>
#include <cuda_bf16.h>

#define N_NODES   50000
#define N_EDGES   800000
#define N_FEAT    128
#define NHID      64
#define NGRAPHS   512
#define KPOOL     30
#define NCLASSES  10

// ---------------- device scratch ----------------
__device__ __align__(16) float g_y[N_NODES * NHID];   // projected neighbor feats (h @ Wl)
__device__ __align__(16) float g_z[N_NODES * NHID];   // self term (h @ Wr + b)
__device__ __align__(16) float g_h[N_NODES * NHID];   // layer output
__device__ __align__(16) int   g_src[N_EDGES];
__device__ __align__(16) int   g_dst[N_EDGES];
__device__ __align__(16) int   g_csrc[N_EDGES];       // CSR: src ids bucketed by dst
__device__ __align__(16) int   g_degi[N_NODES];
__device__ __align__(16) int   g_rowoff[N_NODES];     // exclusive prefix of degi
__device__ __align__(16) int   g_cursor[N_NODES];
__device__ __align__(16) int   g_counts[NGRAPHS];
__device__ __align__(16) int   g_starts[NGRAPHS];
__device__ __align__(16) float g_pool[NGRAPHS * NHID * KPOOL];  // [g][c][t]
__device__ int g_is64_ei;
__device__ int g_is64_batch;

// ---------------- dtype detection (int64 request may have yielded int32) ----------------
__global__ void k_detect(const void* ei, const void* batch) {
    if (threadIdx.x != 0 || blockIdx.x != 0) return;
    const long long* e64 = (const long long*)ei;
    int ok = 1;
    for (int i = 0; i < 1024; i++) {
        long long v = e64[i];
        if (v < 0 || v >= N_NODES) { ok = 0; break; }
    }
    g_is64_ei = ok;
    const long long* b64 = (const long long*)batch;
    int okb = 1;
    for (int i = 0; i < 1024; i++) {
        long long v = b64[i];
        if (v < 0 || v >= NGRAPHS) { okb = 0; break; }
    }
    g_is64_batch = okb;
}

// ---------------- zero int counters ----------------
__global__ void k_zero_ints() {
    int i = blockIdx.x * blockDim.x + threadIdx.x;
    if (i < N_NODES) g_degi[i] = 0;
    if (i < NGRAPHS) g_counts[i] = 0;
}

// ---------------- edge convert + degree + graph counts (dtype-adaptive) ----------------
__global__ void k_prep(const void* __restrict__ ei,
                       const void* __restrict__ batch) {
    int i = blockIdx.x * blockDim.x + threadIdx.x;
    if (i < N_EDGES) {
        int s, d;
        if (g_is64_ei) {
            s = (int)((const long long*)ei)[i];
            d = (int)((const long long*)ei)[N_EDGES + i];
        } else {
            s = ((const int*)ei)[i];
            d = ((const int*)ei)[N_EDGES + i];
        }
        g_src[i] = s;
        g_dst[i] = d;
        atomicAdd(&g_degi[d], 1);
    }
    if (i < N_NODES) {
        int b = g_is64_batch ? (int)((const long long*)batch)[i]
                             : ((const int*)batch)[i];
        atomicAdd(&g_counts[b], 1);
    }
}

// ---------------- scan graph counts -> starts (512, 1 block) ----------------
__global__ void k_scan_graphs() {
    __shared__ int s[NGRAPHS];
    int t = threadIdx.x;
    int myc = g_counts[t];
    s[t] = myc;
    __syncthreads();
    for (int off = 1; off < NGRAPHS; off <<= 1) {
        int v = (t >= off) ? s[t - off] : 0;
        __syncthreads();
        s[t] += v;
        __syncthreads();
    }
    g_starts[t] = s[t] - myc;
}

// ---------------- scan node degrees -> rowoff, init cursor (1 block, 1024 thr) ----------------
__global__ __launch_bounds__(1024) void k_scan_nodes() {
    __shared__ int part[1024];
    const int C = (N_NODES + 1023) / 1024;   // 49
    const int t = threadIdx.x;
    const int base = t * C;
    int sum = 0;
    for (int i = 0; i < C; i++) {
        int idx = base + i;
        if (idx < N_NODES) sum += g_degi[idx];
    }
    part[t] = sum;
    __syncthreads();
    for (int off = 1; off < 1024; off <<= 1) {
        int v = (t >= off) ? part[t - off] : 0;
        __syncthreads();
        part[t] += v;
        __syncthreads();
    }
    int run = part[t] - sum;    // exclusive prefix of this chunk
    for (int i = 0; i < C; i++) {
        int idx = base + i;
        if (idx < N_NODES) {
            g_rowoff[idx] = run;
            g_cursor[idx] = run;
            run += g_degi[idx];
        }
    }
}

// ---------------- fill CSR buckets ----------------
__global__ void k_fill() {
    int i = blockIdx.x * blockDim.x + threadIdx.x;
    if (i >= N_EDGES) return;
    int d = g_dst[i];
    int pos = atomicAdd(&g_cursor[d], 1);
    g_csrc[pos] = g_src[i];
}

// ---------------- dual GEMM: g_y = in@Wl ; g_z = in@Wr + b ----------------
// 32 rows/block, 256 threads; thread owns 8 rows x 2 cols of one output matrix.
template <int KIN>
__global__ __launch_bounds__(256) void k_gemm(const float* __restrict__ in,
                                              const float* __restrict__ Wl,
                                              const float* __restrict__ Wr,
                                              const float* __restrict__ bias) {
    __shared__ float xs[32][KIN];
    const float* __restrict__ src = in ? in : g_h;
    const int row0 = blockIdx.x * 32;
    const int tid  = threadIdx.x;

    for (int i = tid; i < 32 * KIN; i += 256) {
        int r = i / KIN, k = i % KIN;
        int row = row0 + r;
        xs[r][k] = (row < N_NODES) ? src[(size_t)row * KIN + k] : 0.f;
    }
    __syncthreads();

    const int c  = tid & 31;        // cols c and c+32
    const int m  = (tid >> 5) & 1;  // 0: Wl->y, 1: Wr->z
    const int rg = tid >> 6;        // row group 0..3
    const float* __restrict__ W = m ? Wr : Wl;

    float acc0[8], acc1[8];
#pragma unroll
    for (int r = 0; r < 8; r++) { acc0[r] = 0.f; acc1[r] = 0.f; }

    for (int k = 0; k < KIN; k++) {
        float w0 = __ldg(&W[k * NHID + c]);
        float w1 = __ldg(&W[k * NHID + c + 32]);
#pragma unroll
        for (int r = 0; r < 8; r++) {
            float xv = xs[rg * 8 + r][k];
            acc0[r] = fmaf(xv, w0, acc0[r]);
            acc1[r] = fmaf(xv, w1, acc1[r]);
        }
    }

    float b0 = m ? __ldg(&bias[c])      : 0.f;
    float b1 = m ? __ldg(&bias[c + 32]) : 0.f;
    float* __restrict__ out = m ? g_z : g_y;
#pragma unroll
    for (int r = 0; r < 8; r++) {
        int row = row0 + rg * 8 + r;
        if (row < N_NODES) {
            out[(size_t)row * NHID + c]      = acc0[r] + b0;
            out[(size_t)row * NHID + c + 32] = acc1[r] + b1;
        }
    }
}

// ---------------- gather aggregation + combine: one warp per node ----------------
// h[n] = relu( (sum_{e in CSR[n]} y[csrc[e]]) / max(deg,1) + z[n] )
__global__ __launch_bounds__(256) void k_agg() {
    const int warp = (blockIdx.x * 256 + threadIdx.x) >> 5;
    const int lane = threadIdx.x & 31;
    if (warp >= N_NODES) return;

    const int beg = g_rowoff[warp];
    const int deg = g_degi[warp];
    const int end = beg + deg;

    const float2* __restrict__ y2 = reinterpret_cast<const float2*>(g_y);
    float ax0 = 0.f, ay0 = 0.f, ax1 = 0.f, ay1 = 0.f;
    float ax2 = 0.f, ay2 = 0.f, ax3 = 0.f, ay3 = 0.f;

    int e = beg;
    for (; e + 3 < end; e += 4) {
        int s0 = __ldg(&g_csrc[e]);
        int s1 = __ldg(&g_csrc[e + 1]);
        int s2 = __ldg(&g_csrc[e + 2]);
        int s3 = __ldg(&g_csrc[e + 3]);
        float2 v0 = __ldg(&y2[(size_t)s0 * 32 + lane]);
        float2 v1 = __ldg(&y2[(size_t)s1 * 32 + lane]);
        float2 v2 = __ldg(&y2[(size_t)s2 * 32 + lane]);
        float2 v3 = __ldg(&y2[(size_t)s3 * 32 + lane]);
        ax0 += v0.x; ay0 += v0.y;
        ax1 += v1.x; ay1 += v1.y;
        ax2 += v2.x; ay2 += v2.y;
        ax3 += v3.x; ay3 += v3.y;
    }
    for (; e < end; e++) {
        int s = __ldg(&g_csrc[e]);
        float2 v = __ldg(&y2[(size_t)s * 32 + lane]);
        ax0 += v.x; ay0 += v.y;
    }

    float inv = 1.f / fmaxf((float)deg, 1.f);
    float2 z = __ldg(&reinterpret_cast<const float2*>(g_z)[(size_t)warp * 32 + lane]);
    float2 ho;
    ho.x = fmaxf(fmaf((ax0 + ax1) + (ax2 + ax3), inv, z.x), 0.f);
    ho.y = fmaxf(fmaf((ay0 + ay1) + (ay2 + ay3), inv, z.y), 0.f);
    reinterpret_cast<float2*>(g_h)[(size_t)warp * 32 + lane] = ho;
}

// ---------------- sort pool: top-K by last channel, rank via counting ----------------
__global__ __launch_bounds__(128) void k_sortpool() {
    const int g = blockIdx.x;
    const int tid = threadIdx.x;
    const int s = g_starts[g];
    const int cnt = g_counts[g];

    float* pool = g_pool + (size_t)g * NHID * KPOOL;
    for (int i = tid; i < NHID * KPOOL; i += 128) pool[i] = 0.f;

    __shared__ float skey[2048];
    const int cap = (cnt < 2048) ? cnt : 2048;
    for (int i = tid; i < cap; i += 128)
        skey[i] = g_h[(size_t)(s + i) * NHID + (NHID - 1)];
    __syncthreads();

    for (int i = tid; i < cnt; i += 128) {
        float ki = (i < cap) ? skey[i] : g_h[(size_t)(s + i) * NHID + (NHID - 1)];
        int rank = 0;
        for (int j = 0; j < cnt; j++) {
            float kj = (j < cap) ? skey[j] : g_h[(size_t)(s + j) * NHID + (NHID - 1)];
            // descending by key; stable tie-break ascending index (matches lexsort)
            rank += (kj > ki) || (kj == ki && j < i);
            if (rank >= KPOOL) break;
        }
        if (rank < KPOOL) {
            const float* hr = g_h + (size_t)(s + i) * NHID;
#pragma unroll 4
            for (int c = 0; c < NHID; c++)
                pool[c * KPOOL + rank] = hr[c];
        }
    }
}

// ---------------- fused head: conv1d(k=5)+relu + lin1+relu + lin2 + log_softmax ----------------
__global__ __launch_bounds__(256) void k_head(const float* __restrict__ convw,
                                              const float* __restrict__ convb,
                                              const float* __restrict__ lin1w,
                                              const float* __restrict__ lin1b,
                                              const float* __restrict__ lin2w,
                                              const float* __restrict__ lin2b,
                                              float* __restrict__ out) {
    const int g = blockIdx.x;
    const int tid = threadIdx.x;

    __shared__ float sp[NHID * KPOOL];
    __shared__ float sconv[32 * 26];
    __shared__ float sred[256];
    __shared__ float sf[NHID];
    __shared__ float slog[NCLASSES];
    __shared__ float smax, slse;

    const float* pool = g_pool + (size_t)g * NHID * KPOOL;
    for (int i = tid; i < NHID * KPOOL; i += 256) sp[i] = pool[i];
    __syncthreads();

    for (int idx = tid; idx < 32 * 26; idx += 256) {
        int o = idx / 26, t = idx % 26;
        float acc = __ldg(&convb[o]);
        const float* wbase = convw + (size_t)o * NHID * 5;
        for (int c = 0; c < NHID; c++) {
            const float* wrow = wbase + c * 5;
            const float* prow = sp + c * KPOOL + t;
#pragma unroll
            for (int kk = 0; kk < 5; kk++)
                acc = fmaf(prow[kk], __ldg(&wrow[kk]), acc);
        }
        sconv[idx] = fmaxf(acc, 0.f);
    }
    __syncthreads();

    {   // lin1: 832 x 64, 4-way K split
        int j = tid & 63, part = tid >> 6;
        float acc = 0.f;
        for (int i = part; i < 32 * 26; i += 4)
            acc = fmaf(sconv[i], __ldg(&lin1w[(size_t)i * NHID + j]), acc);
        sred[tid] = acc;
        __syncthreads();
        if (part == 0) {
            float v = sred[j] + sred[j + 64] + sred[j + 128] + sred[j + 192];
            sf[j] = fmaxf(v + __ldg(&lin1b[j]), 0.f);
        }
        __syncthreads();
    }

    if (tid < NCLASSES) {
        float acc = __ldg(&lin2b[tid]);
        for (int j = 0; j < NHID; j++)
            acc = fmaf(sf[j], __ldg(&lin2w[j * NCLASSES + tid]), acc);
        slog[tid] = acc;
    }
    __syncthreads();
    if (tid == 0) {
        float mx = slog[0];
        for (int k = 1; k < NCLASSES; k++) mx = fmaxf(mx, slog[k]);
        float sum = 0.f;
        for (int k = 0; k < NCLASSES; k++) sum += expf(slog[k] - mx);
        smax = mx;
        slse = logf(sum);
    }
    __syncthreads();
    if (tid < NCLASSES)
        out[(size_t)g * NCLASSES + tid] = slog[tid] - smax - slse;
}

// ---------------- host launcher ----------------
extern "C" void kernel_launch(void* const* d_in, const int* in_sizes, int n_in,
                              void* d_out, int out_size) {
    const float* x     = (const float*)d_in[0];
    const void*  ei    = d_in[1];
    const void*  batch = d_in[2];
    const float* W1l = (const float*)d_in[3];
    const float* b1  = (const float*)d_in[4];
    const float* W1r = (const float*)d_in[5];
    const float* W2l = (const float*)d_in[6];
    const float* b2  = (const float*)d_in[7];
    const float* W2r = (const float*)d_in[8];
    const float* W3l = (const float*)d_in[9];
    const float* b3  = (const float*)d_in[10];
    const float* W3r = (const float*)d_in[11];
    const float* convw = (const float*)d_in[12];
    const float* convb = (const float*)d_in[13];
    const float* lin1w = (const float*)d_in[14];
    const float* lin1b = (const float*)d_in[15];
    const float* lin2w = (const float*)d_in[16];
    const float* lin2b = (const float*)d_in[17];
    float* out = (float*)d_out;

    // ---- prep: dtype detection, degrees, counts, CSR ----
    k_detect<<<1, 32>>>(ei, batch);
    k_zero_ints<<<(N_NODES + 255) / 256, 256>>>();
    k_prep<<<(N_EDGES + 255) / 256, 256>>>(ei, batch);
    k_scan_graphs<<<1, NGRAPHS>>>();
    k_scan_nodes<<<1, 1024>>>();
    k_fill<<<(N_EDGES + 255) / 256, 256>>>();

    const int GB = (N_NODES + 31) / 32;                 // gemm blocks
    const int AB = (N_NODES * 32 + 255) / 256;          // agg blocks (warp/node)

    // ---- layer 1 ----
    k_gemm<N_FEAT><<<GB, 256>>>(x, W1l, W1r, b1);
    k_agg<<<AB, 256>>>();
    // ---- layer 2 ----
    k_gemm<NHID><<<GB, 256>>>(nullptr, W2l, W2r, b2);
    k_agg<<<AB, 256>>>();
    // ---- layer 3 ----
    k_gemm<NHID><<<GB, 256>>>(nullptr, W3l, W3r, b3);
    k_agg<<<AB, 256>>>();

    // ---- sort-pool + head ----
    k_sortpool<<<NGRAPHS, 128>>>();
    k_head<<<NGRAPHS, 256>>>(convw, convb, lin1w, lin1b, lin2w, lin2b, out);
}